// round 11
// baseline (speedup 1.0000x reference)
#include <cuda_runtime.h>
#include <cstdint>

#define IMG_H 512
#define IMG_W 512

// evict_last policy handle (createpolicy) + cache_hint loads:
// pins x/f lines in L2 across graph replays.
__device__ __forceinline__ uint64_t mk_policy_el() {
    uint64_t pol;
    asm("createpolicy.fractional.L2::evict_last.b64 %0, 1.0;" : "=l"(pol));
    return pol;
}
__device__ __forceinline__ float4 ldg_el4(const float* p, uint64_t pol) {
    float4 v;
    asm("ld.global.nc.L2::cache_hint.v4.f32 {%0,%1,%2,%3}, [%4], %5;"
        : "=f"(v.x), "=f"(v.y), "=f"(v.z), "=f"(v.w) : "l"(p), "l"(pol));
    return v;
}

__global__ __launch_bounds__(128)
void cheby_smooth_kernel(const float* __restrict__ x,
                         const float* __restrict__ f,
                         const float* __restrict__ kA,
                         float* __restrict__ out)
{
    const int b    = blockIdx.z;
    const int lane = threadIdx.x;                                 // blockDim.x == 32
    const int r0   = (blockIdx.y * 4 + threadIdx.y) * 8;          // first of 8 output rows
    const int c0   = (blockIdx.x * 32 + lane) * 4;                // first of 4 output cols

    __shared__ float k[9];
    if (threadIdx.y == 0 && lane < 9)
        k[lane] = kA[b * 9 + lane];
    __syncthreads();

    const uint64_t pol = mk_policy_el();

    const size_t base = (size_t)b * IMG_H * IMG_W;
    const float* __restrict__ xb = x + base;
    const float* __restrict__ fb = f + base;
    float* __restrict__ ob = out + base;

    // ---- Phase 1: issue ALL global loads up front (branch-free, max MLP) ----
    float4 mid[10];
    float  lf[10], rt[10];

    #pragma unroll
    for (int i = 0; i < 10; ++i) {
        const int rr = r0 - 1 + i;
        const bool valid = (rr >= 0) && (rr < IMG_H);
        const int rc = valid ? rr : (rr < 0 ? 0 : IMG_H - 1);     // clamped (always-safe) row
        const float* __restrict__ row = xb + (size_t)rc * IMG_W;
        float4 v = ldg_el4(row + c0, pol);
        mid[i].x = valid ? v.x : 0.f;
        mid[i].y = valid ? v.y : 0.f;
        mid[i].z = valid ? v.z : 0.f;
        mid[i].w = valid ? v.w : 0.f;
        // Only lanes 0 / 31 need a real boundary element (tiny traffic, default policy).
        lf[i] = (lane == 0  && valid && c0 > 0)         ? row[c0 - 1] : 0.f;
        rt[i] = (lane == 31 && valid && c0 + 4 < IMG_W) ? row[c0 + 4] : 0.f;
    }

    float4 fv[8];
    #pragma unroll
    for (int j = 0; j < 8; ++j)
        fv[j] = ldg_el4(fb + (size_t)(r0 + j) * IMG_W + c0, pol);

    // ---- Phase 2: intra-warp halo exchange ----
    #pragma unroll
    for (int i = 0; i < 10; ++i) {
        const float l = __shfl_up_sync(0xffffffffu, mid[i].w, 1);
        const float r = __shfl_down_sync(0xffffffffu, mid[i].x, 1);
        if (lane != 0)  lf[i] = l;
        if (lane != 31) rt[i] = r;
    }

    // ---- Phase 3: compute 8 output rows ----
    const float inv6 = 1.0f / 6.0f;

    #pragma unroll
    for (int j = 0; j < 8; ++j) {
        float a0 = 0.f, a1 = 0.f, a2 = 0.f, a3 = 0.f;
        #pragma unroll
        for (int t = 0; t < 3; ++t) {
            const int i = j + t;
            const float k0 = k[t * 3 + 0];
            const float k1 = k[t * 3 + 1];
            const float k2 = k[t * 3 + 2];
            a0 = fmaf(lf[i],    k0, fmaf(mid[i].x, k1, fmaf(mid[i].y, k2, a0)));
            a1 = fmaf(mid[i].x, k0, fmaf(mid[i].y, k1, fmaf(mid[i].z, k2, a1)));
            a2 = fmaf(mid[i].y, k0, fmaf(mid[i].z, k1, fmaf(mid[i].w, k2, a2)));
            a3 = fmaf(mid[i].z, k0, fmaf(mid[i].w, k1, fmaf(rt[i],    k2, a3)));
        }
        const float4 xc = mid[j + 1];
        float4 o;
        o.x = xc.x + (fv[j].x - a0) * inv6;
        o.y = xc.y + (fv[j].y - a1) * inv6;
        o.z = xc.z + (fv[j].z - a2) * inv6;
        o.w = xc.w + (fv[j].w - a3) * inv6;
        // Streaming store: don't let output lines displace the pinned x/f read set.
        __stcs(reinterpret_cast<float4*>(ob + (size_t)(r0 + j) * IMG_W + c0), o);
    }
}

extern "C" void kernel_launch(void* const* d_in, const int* in_sizes, int n_in,
                              void* d_out, int out_size)
{
    const float* x  = (const float*)d_in[0];   // [64,1,512,512]
    const float* f  = (const float*)d_in[1];   // [64,1,512,512]
    const float* kA = (const float*)d_in[2];   // [64,1,3,3]
    float* out = (float*)d_out;

    dim3 block(32, 4, 1);
    dim3 grid(IMG_W / (32 * 4), IMG_H / (4 * 8), 64); // (4, 16, 64)
    cheby_smooth_kernel<<<grid, block>>>(x, f, kA, out);
}

// round 12
// speedup vs baseline: 1.3099x; 1.3099x over previous
#include <cuda_runtime.h>
#include <cstdint>

#define IMG_H 512
#define IMG_W 512

// 256-bit global load (sm_10x LDG.E.256): 8 consecutive floats, 32B-aligned.
__device__ __forceinline__ void ldg8(const float* p, float* d) {
    asm("ld.global.v8.b32 {%0,%1,%2,%3,%4,%5,%6,%7}, [%8];"
        : "=f"(d[0]), "=f"(d[1]), "=f"(d[2]), "=f"(d[3]),
          "=f"(d[4]), "=f"(d[5]), "=f"(d[6]), "=f"(d[7])
        : "l"(p));
}

__global__ __launch_bounds__(128)
void cheby_smooth_kernel(const float* __restrict__ x,
                         const float* __restrict__ f,
                         const float* __restrict__ kA,
                         float* __restrict__ out)
{
    const int b    = blockIdx.z;
    const int lane = threadIdx.x;                                  // blockDim.x == 32
    const int r0   = (blockIdx.y * 4 + threadIdx.y) * 4;           // first of 4 output rows
    const int c0   = blockIdx.x * 256 + lane * 8;                  // first of 8 output cols

    __shared__ float k[9];
    if (threadIdx.y == 0 && lane < 9)
        k[lane] = kA[b * 9 + lane];
    __syncthreads();

    const size_t base = (size_t)b * IMG_H * IMG_W;
    const float* __restrict__ xb = x + base;
    const float* __restrict__ fb = f + base;
    float* __restrict__ ob = out + base;

    // ---- Phase 1: ALL loads up front, branch-free (max bytes in flight) ----
    float mid[6][8];
    float lf[6], rt[6];

    #pragma unroll
    for (int i = 0; i < 6; ++i) {
        const int rr = r0 - 1 + i;
        const bool valid = (rr >= 0) && (rr < IMG_H);
        const int rc = rr < 0 ? 0 : (rr >= IMG_H ? IMG_H - 1 : rr);   // always-safe row
        const float* __restrict__ row = xb + (size_t)rc * IMG_W;
        float v[8];
        ldg8(row + c0, v);
        #pragma unroll
        for (int c = 0; c < 8; ++c)
            mid[i][c] = valid ? v[c] : 0.f;
        // Boundary scalars: only lanes 0 / 31 carry real data.
        lf[i] = (lane == 0  && valid && c0 > 0)         ? row[c0 - 1] : 0.f;
        rt[i] = (lane == 31 && valid && c0 + 8 < IMG_W) ? row[c0 + 8] : 0.f;
    }

    float fv[4][8];
    #pragma unroll
    for (int j = 0; j < 4; ++j)
        ldg8(fb + (size_t)(r0 + j) * IMG_W + c0, fv[j]);

    // ---- Phase 2: intra-warp halo exchange ----
    #pragma unroll
    for (int i = 0; i < 6; ++i) {
        const float l = __shfl_up_sync(0xffffffffu, mid[i][7], 1);
        const float r = __shfl_down_sync(0xffffffffu, mid[i][0], 1);
        if (lane != 0)  lf[i] = l;
        if (lane != 31) rt[i] = r;
    }

    // ---- Phase 3: compute 4 output rows x 8 cols ----
    const float inv6 = 1.0f / 6.0f;

    #pragma unroll
    for (int j = 0; j < 4; ++j) {
        float a[8];
        #pragma unroll
        for (int c = 0; c < 8; ++c) a[c] = 0.f;

        #pragma unroll
        for (int t = 0; t < 3; ++t) {
            const int i = j + t;
            const float k0 = k[t * 3 + 0];
            const float k1 = k[t * 3 + 1];
            const float k2 = k[t * 3 + 2];
            // window w[c] = x[rr][c0 + c - 1], c = 0..9
            a[0] = fmaf(lf[i],     k0, fmaf(mid[i][0], k1, fmaf(mid[i][1], k2, a[0])));
            #pragma unroll
            for (int c = 1; c < 7; ++c)
                a[c] = fmaf(mid[i][c-1], k0, fmaf(mid[i][c], k1, fmaf(mid[i][c+1], k2, a[c])));
            a[7] = fmaf(mid[i][6], k0, fmaf(mid[i][7], k1, fmaf(rt[i],     k2, a[7])));
        }

        float* orow = ob + (size_t)(r0 + j) * IMG_W + c0;
        float4 o0, o1;
        o0.x = mid[j+1][0] + (fv[j][0] - a[0]) * inv6;
        o0.y = mid[j+1][1] + (fv[j][1] - a[1]) * inv6;
        o0.z = mid[j+1][2] + (fv[j][2] - a[2]) * inv6;
        o0.w = mid[j+1][3] + (fv[j][3] - a[3]) * inv6;
        o1.x = mid[j+1][4] + (fv[j][4] - a[4]) * inv6;
        o1.y = mid[j+1][5] + (fv[j][5] - a[5]) * inv6;
        o1.z = mid[j+1][6] + (fv[j][6] - a[6]) * inv6;
        o1.w = mid[j+1][7] + (fv[j][7] - a[7]) * inv6;
        *reinterpret_cast<float4*>(orow)     = o0;
        *reinterpret_cast<float4*>(orow + 4) = o1;
    }
}

extern "C" void kernel_launch(void* const* d_in, const int* in_sizes, int n_in,
                              void* d_out, int out_size)
{
    const float* x  = (const float*)d_in[0];   // [64,1,512,512]
    const float* f  = (const float*)d_in[1];   // [64,1,512,512]
    const float* kA = (const float*)d_in[2];   // [64,1,3,3]
    float* out = (float*)d_out;

    dim3 block(32, 4, 1);
    dim3 grid(IMG_W / 256, IMG_H / 16, 64);   // (2, 32, 64) = 4096 CTAs
    cheby_smooth_kernel<<<grid, block>>>(x, f, kA, out);
}